// round 1
// baseline (speedup 1.0000x reference)
#include <cuda_runtime.h>

#define HID    1024
#define BATCH  32
#define LAYERS 3
#define OUTDIM 2500
#define GRID_N 50
#define MODES  32
#define TIME   64

#define CHUNK 128
#define CPAD  129   // +1 pad -> conflict-free lane-indexed smem reads

// ---------------- persistent device state (no allocs allowed) ----------------
__device__ float g_h[2][LAYERS][BATCH][HID];   // double-buffered hidden state
__device__ float g_x[BATCH][HID];              // spectral-crop feedback input
__device__ float g_ct[MODES][GRID_N];          // cos(2*pi*k*n/50), k = idx-16
__device__ float g_st[MODES][GRID_N];          // sin(2*pi*k*n/50)

// ---------------- init: zero h, copy x, build twiddle table ------------------
__global__ void init_kernel(const float* __restrict__ x)
{
    int tid    = blockIdx.x * blockDim.x + threadIdx.x;
    int stride = gridDim.x * blockDim.x;

    float* hflat = (float*)g_h;
    for (int i = tid; i < 2 * LAYERS * BATCH * HID; i += stride) hflat[i] = 0.0f;

    float* xflat = (float*)g_x;
    for (int i = tid; i < BATCH * HID; i += stride) xflat[i] = x[i];

    for (int i = tid; i < MODES * GRID_N; i += stride) {
        int t = i / GRID_N;
        int n = i % GRID_N;
        float arg = 2.0f * (float)(t - 16) * (float)n / 50.0f;  // units of pi
        g_ct[t][n] = cospif(arg);
        g_st[t][n] = sinpif(arg);
    }
}

// ---------------- fused GRU layer: one warp = one unit, lane = batch ---------
// grid = 128 blocks * 8 warps = 1024 units. Six 1024-length dots per unit.
__global__ __launch_bounds__(256) void gru_kernel(
    int layer, int src,                         // parity of source h buffer
    const float* __restrict__ W_ih_all,         // [L][3H][H]
    const float* __restrict__ W_hh_all,
    const float* __restrict__ b_ih_all,         // [L][3H]
    const float* __restrict__ b_hh_all)
{
    __shared__ float xs[BATCH * CPAD];
    __shared__ float hs[BATCH * CPAD];

    const int dst  = src ^ 1;
    const int warp = threadIdx.x >> 5;
    const int lane = threadIdx.x & 31;          // batch index
    const int u    = blockIdx.x * 8 + warp;     // unit index

    const float* inp = (layer == 0) ? &g_x[0][0] : &g_h[dst][layer - 1][0][0];
    const float* hin = &g_h[src][layer][0][0];
    float*       hout = &g_h[dst][layer][0][0];

    const float* Wih = W_ih_all + (size_t)layer * 3 * HID * HID;
    const float* Whh = W_hh_all + (size_t)layer * 3 * HID * HID;

    const float* w0 = Wih + (size_t)u * HID;
    const float* w1 = Wih + (size_t)(u +     HID) * HID;
    const float* w2 = Wih + (size_t)(u + 2 * HID) * HID;
    const float* w3 = Whh + (size_t)u * HID;
    const float* w4 = Whh + (size_t)(u +     HID) * HID;
    const float* w5 = Whh + (size_t)(u + 2 * HID) * HID;

    float a0 = 0.f, a1 = 0.f, a2 = 0.f, a3 = 0.f, a4 = 0.f, a5 = 0.f;

    for (int k0 = 0; k0 < HID; k0 += CHUNK) {
        __syncthreads();
        for (int i = threadIdx.x; i < BATCH * CHUNK; i += 256) {
            int b  = i >> 7;          // CHUNK = 128
            int kk = i & (CHUNK - 1);
            xs[b * CPAD + kk] = inp[b * HID + k0 + kk];
            hs[b * CPAD + kk] = hin[b * HID + k0 + kk];
        }
        __syncthreads();

        #pragma unroll 4
        for (int kk = 0; kk < CHUNK; kk += 4) {
            int k = k0 + kk;
            float4 v0 = *(const float4*)(w0 + k);
            float4 v1 = *(const float4*)(w1 + k);
            float4 v2 = *(const float4*)(w2 + k);
            float4 v3 = *(const float4*)(w3 + k);
            float4 v4 = *(const float4*)(w4 + k);
            float4 v5 = *(const float4*)(w5 + k);

            float x0 = xs[lane * CPAD + kk + 0];
            float x1 = xs[lane * CPAD + kk + 1];
            float x2 = xs[lane * CPAD + kk + 2];
            float x3 = xs[lane * CPAD + kk + 3];
            float h0 = hs[lane * CPAD + kk + 0];
            float h1 = hs[lane * CPAD + kk + 1];
            float h2 = hs[lane * CPAD + kk + 2];
            float h3 = hs[lane * CPAD + kk + 3];

            a0 += v0.x * x0 + v0.y * x1 + v0.z * x2 + v0.w * x3;
            a1 += v1.x * x0 + v1.y * x1 + v1.z * x2 + v1.w * x3;
            a2 += v2.x * x0 + v2.y * x1 + v2.z * x2 + v2.w * x3;
            a3 += v3.x * h0 + v3.y * h1 + v3.z * h2 + v3.w * h3;
            a4 += v4.x * h0 + v4.y * h1 + v4.z * h2 + v4.w * h3;
            a5 += v5.x * h0 + v5.y * h1 + v5.z * h2 + v5.w * h3;
        }
    }

    const float* bih = b_ih_all + layer * 3 * HID;
    const float* bhh = b_hh_all + layer * 3 * HID;

    float i_r = a0 + bih[u];
    float i_z = a1 + bih[u + HID];
    float i_n = a2 + bih[u + 2 * HID];
    float h_r = a3 + bhh[u];
    float h_z = a4 + bhh[u + HID];
    float h_n = a5 + bhh[u + 2 * HID];

    float r = 1.0f / (1.0f + expf(-(i_r + h_r)));
    float z = 1.0f / (1.0f + expf(-(i_z + h_z)));
    float n = tanhf(i_n + r * h_n);

    float h_old = hin[lane * HID + u];
    hout[lane * HID + u] = (1.0f - z) * n + z * h_old;
}

// ---------------- FC layer: warp = 2 outputs, lane = batch -------------------
__global__ __launch_bounds__(256) void fc_kernel(
    int src,                                   // parity: h produced this step is in src^1
    const float* __restrict__ fc_w,            // [OUTDIM][HID]
    const float* __restrict__ fc_b,
    float* __restrict__ outp)                  // [BATCH][OUTDIM] slice of d_out
{
    __shared__ float hsm[BATCH * CPAD];

    const int dst  = src ^ 1;
    const int warp = threadIdx.x >> 5;
    const int lane = threadIdx.x & 31;
    const int o0   = (blockIdx.x * 8 + warp) * 2;
    const int o1   = o0 + 1;

    const float* hvec = &g_h[dst][LAYERS - 1][0][0];
    const float* wr0  = fc_w + (size_t)o0 * HID;
    const float* wr1  = fc_w + (size_t)o1 * HID;

    float a0 = 0.f, a1 = 0.f;

    for (int k0 = 0; k0 < HID; k0 += CHUNK) {
        __syncthreads();
        for (int i = threadIdx.x; i < BATCH * CHUNK; i += 256) {
            int b  = i >> 7;
            int kk = i & (CHUNK - 1);
            hsm[b * CPAD + kk] = hvec[b * HID + k0 + kk];
        }
        __syncthreads();

        #pragma unroll 4
        for (int kk = 0; kk < CHUNK; kk += 4) {
            int k = k0 + kk;
            float4 v0 = (o0 < OUTDIM) ? *(const float4*)(wr0 + k) : make_float4(0, 0, 0, 0);
            float4 v1 = (o1 < OUTDIM) ? *(const float4*)(wr1 + k) : make_float4(0, 0, 0, 0);
            float x0 = hsm[lane * CPAD + kk + 0];
            float x1 = hsm[lane * CPAD + kk + 1];
            float x2 = hsm[lane * CPAD + kk + 2];
            float x3 = hsm[lane * CPAD + kk + 3];
            a0 += v0.x * x0 + v0.y * x1 + v0.z * x2 + v0.w * x3;
            a1 += v1.x * x0 + v1.y * x1 + v1.z * x2 + v1.w * x3;
        }
    }

    if (o0 < OUTDIM) outp[lane * OUTDIM + o0] = a0 + fc_b[o0];
    if (o1 < OUTDIM) outp[lane * OUTDIM + o1] = a1 + fc_b[o1];
}

// ---------------- spectral crop: separable real-part 2D DFT ------------------
// x_next[b, p*32+q] = Re F[kp, kq], kp = p-16, kq = q-16 (fftshift + crop).
__global__ __launch_bounds__(256) void spectral_kernel(const float* __restrict__ outp)
{
    const int b = blockIdx.x;
    __shared__ float a[OUTDIM];
    __shared__ float cre[GRID_N * MODES];
    __shared__ float cim[GRID_N * MODES];

    for (int i = threadIdx.x; i < OUTDIM; i += blockDim.x)
        a[i] = outp[b * OUTDIM + i];
    __syncthreads();

    // stage 1: DFT along n for the 32 kept q-frequencies
    for (int i = threadIdx.x; i < GRID_N * MODES; i += blockDim.x) {
        int m = i / MODES;
        int q = i % MODES;
        float sre = 0.f, sim = 0.f;
        #pragma unroll 5
        for (int n = 0; n < GRID_N; n++) {
            float v = a[m * GRID_N + n];
            sre += v * g_ct[q][n];
            sim -= v * g_st[q][n];
        }
        cre[m * MODES + q] = sre;
        cim[m * MODES + q] = sim;
    }
    __syncthreads();

    // stage 2: DFT along m, keep real part. Re(e^{-i t}(x+iy)) = cos*x + sin*y
    for (int i = threadIdx.x; i < MODES * MODES; i += blockDim.x) {
        int p = i / MODES;
        int q = i % MODES;
        float s = 0.f;
        #pragma unroll 5
        for (int m = 0; m < GRID_N; m++)
            s += g_ct[p][m] * cre[m * MODES + q] + g_st[p][m] * cim[m * MODES + q];
        g_x[b][i] = s;
    }
}

// ---------------- driver -----------------------------------------------------
extern "C" void kernel_launch(void* const* d_in, const int* in_sizes, int n_in,
                              void* d_out, int out_size)
{
    const float* x     = (const float*)d_in[0];
    const float* W_ih  = (const float*)d_in[1];
    const float* W_hh  = (const float*)d_in[2];
    const float* b_ih  = (const float*)d_in[3];
    const float* b_hh  = (const float*)d_in[4];
    const float* fc_w  = (const float*)d_in[5];
    const float* fc_b  = (const float*)d_in[6];
    float*       out   = (float*)d_out;

    init_kernel<<<64, 256>>>(x);

    for (int t = 0; t < TIME; t++) {
        int src = t & 1;
        float* outp = out + (size_t)t * BATCH * OUTDIM;

        gru_kernel<<<128, 256>>>(0, src, W_ih, W_hh, b_ih, b_hh);
        gru_kernel<<<128, 256>>>(1, src, W_ih, W_hh, b_ih, b_hh);
        gru_kernel<<<128, 256>>>(2, src, W_ih, W_hh, b_ih, b_hh);
        fc_kernel<<<157, 256>>>(src, fc_w, fc_b, outp);
        spectral_kernel<<<BATCH, 256>>>(outp);
    }
}

// round 2
// speedup vs baseline: 3.6743x; 3.6743x over previous
#include <cuda_runtime.h>
#include <cstdint>

#define HID    1024
#define BATCH  32
#define LAYERS 3
#define OUTDIM 2500
#define GRID_N 50
#define MODES  32
#define TIME   64

#define KS      16          // K-slices for GRU gemm (8 ih + 8 hh)
#define KSLICE  128         // K per slice (GRU)
#define KS_FC   16
#define KSLICE_FC 64
#define M_FC_PAD 2512

// ---------------- persistent device state ------------------------------------
__device__ float g_h[2][LAYERS][BATCH][HID];     // double-buffered hidden state
__device__ float g_x[BATCH][HID];                // spectral feedback input
__device__ float g_ct[MODES][GRID_N];
__device__ float g_st[MODES][GRID_N];
__device__ float g_part[KS * 3072 * 32];         // split-K partials (6.3 MB)

// ---------------- helpers ----------------------------------------------------
__device__ __forceinline__ uint32_t f2tf(float f) {
    uint32_t u;
    asm("cvt.rna.tf32.f32 %0, %1;" : "=r"(u) : "f"(f));
    return u;
}

__device__ __forceinline__ void mma1688(float& c0, float& c1, float& c2, float& c3,
                                        uint32_t a0, uint32_t a1, uint32_t a2, uint32_t a3,
                                        uint32_t b0, uint32_t b1) {
    asm volatile(
        "mma.sync.aligned.m16n8k8.row.col.f32.tf32.tf32.f32 "
        "{%0,%1,%2,%3}, {%4,%5,%6,%7}, {%8,%9}, {%0,%1,%2,%3};"
        : "+f"(c0), "+f"(c1), "+f"(c2), "+f"(c3)
        : "r"(a0), "r"(a1), "r"(a2), "r"(a3), "r"(b0), "r"(b1));
}

// ---------------- init -------------------------------------------------------
__global__ void init_kernel(const float* __restrict__ x)
{
    int tid    = blockIdx.x * blockDim.x + threadIdx.x;
    int stride = gridDim.x * blockDim.x;

    float* hflat = (float*)g_h;
    for (int i = tid; i < 2 * LAYERS * BATCH * HID; i += stride) hflat[i] = 0.0f;

    float* xflat = (float*)g_x;
    for (int i = tid; i < BATCH * HID; i += stride) xflat[i] = x[i];

    for (int i = tid; i < MODES * GRID_N; i += stride) {
        int t = i / GRID_N;
        int n = i % GRID_N;
        float arg = 2.0f * (float)(t - 16) * (float)n / 50.0f;  // units of pi
        g_ct[t][n] = cospif(arg);
        g_st[t][n] = sinpif(arg);
    }
}

// ---------------- GRU gate GEMM (split-K, 3xTF32) ----------------------------
// grid (24, 16): x = m-block (128 rows), y = K-slice. Slices 0-7: W_ih @ x,
// slices 8-15: W_hh @ h. Partials -> g_part[ks][m][n] (n = batch).
__global__ __launch_bounds__(256) void gru_gemm(
    int layer, int src,
    const float* __restrict__ W_ih_all,
    const float* __restrict__ W_hh_all)
{
    __shared__ float vhi[BATCH][KSLICE + 4];
    __shared__ float vlo[BATCH][KSLICE + 4];

    const int dst  = src ^ 1;
    const int ks   = blockIdx.y;
    const int warp = threadIdx.x >> 5;
    const int lane = threadIdx.x & 31;
    const int g    = lane >> 2;      // groupID
    const int t    = lane & 3;       // threadID_in_group
    const int m0   = blockIdx.x * 128 + warp * 16;
    const int koff = (ks & 7) * KSLICE;

    // stage B slice (transposed, hi/lo split)
    const float* bsrc;
    if (ks < 8) {
        bsrc = (layer == 0) ? &g_x[0][0] : &g_h[dst][layer - 1][0][0];
    } else {
        bsrc = &g_h[src][layer][0][0];
    }
    for (int i = threadIdx.x; i < BATCH * KSLICE; i += 256) {
        int n = i >> 7;              // KSLICE = 128
        int k = i & (KSLICE - 1);
        float f  = bsrc[n * HID + koff + k];
        uint32_t hu = f2tf(f);
        float hf = __uint_as_float(hu);
        vhi[n][k] = hf;
        vlo[n][k] = __uint_as_float(f2tf(f - hf));
    }
    __syncthreads();

    // A row pointers (weights, fp32 in global; L2-resident)
    const float* A = ((ks < 8) ? W_ih_all : W_hh_all) + (size_t)layer * 3 * HID * HID;
    const float* pA0 = A + (size_t)(m0 + g) * HID + koff + t;
    const float* pA1 = pA0 + (size_t)8 * HID;

    float c[4][4] = {};

    #pragma unroll 4
    for (int k0 = 0; k0 < KSLICE; k0 += 8) {
        float f0 = pA0[k0];
        float f1 = pA1[k0];
        float f2 = pA0[k0 + 4];
        float f3 = pA1[k0 + 4];

        uint32_t ah0 = f2tf(f0), ah1 = f2tf(f1), ah2 = f2tf(f2), ah3 = f2tf(f3);
        uint32_t al0 = f2tf(f0 - __uint_as_float(ah0));
        uint32_t al1 = f2tf(f1 - __uint_as_float(ah1));
        uint32_t al2 = f2tf(f2 - __uint_as_float(ah2));
        uint32_t al3 = f2tf(f3 - __uint_as_float(ah3));

        #pragma unroll
        for (int nt = 0; nt < 4; nt++) {
            int n = nt * 8 + g;
            uint32_t bh0 = __float_as_uint(vhi[n][k0 + t]);
            uint32_t bh1 = __float_as_uint(vhi[n][k0 + t + 4]);
            uint32_t bl0 = __float_as_uint(vlo[n][k0 + t]);
            uint32_t bl1 = __float_as_uint(vlo[n][k0 + t + 4]);
            mma1688(c[nt][0], c[nt][1], c[nt][2], c[nt][3], ah0, ah1, ah2, ah3, bh0, bh1);
            mma1688(c[nt][0], c[nt][1], c[nt][2], c[nt][3], ah0, ah1, ah2, ah3, bl0, bl1);
            mma1688(c[nt][0], c[nt][1], c[nt][2], c[nt][3], al0, al1, al2, al3, bh0, bh1);
        }
    }

    // store partials: g_part[ks][m][n], n contiguous
    #pragma unroll
    for (int nt = 0; nt < 4; nt++) {
        int n = nt * 8 + 2 * t;
        float* base = g_part + ((size_t)ks * 3072 + (m0 + g)) * 32 + n;
        *(float2*)base            = make_float2(c[nt][0], c[nt][1]);
        *(float2*)(base + 8 * 32) = make_float2(c[nt][2], c[nt][3]);
    }
}

// ---------------- GRU cell pointwise: reduce partials + gate math ------------
__global__ __launch_bounds__(256) void gru_cell(
    int layer, int src,
    const float* __restrict__ b_ih_all,
    const float* __restrict__ b_hh_all)
{
    const int dst = src ^ 1;
    const int gid = blockIdx.x * 256 + threadIdx.x;
    const int b   = gid & 31;
    const int u   = gid >> 5;

    float i_r = 0.f, i_z = 0.f, i_n = 0.f, h_r = 0.f, h_z = 0.f, h_n = 0.f;
    #pragma unroll
    for (int ks = 0; ks < 8; ks++) {
        const float* p = g_part + (size_t)ks * 3072 * 32;
        i_r += p[(u)          * 32 + b];
        i_z += p[(u + 1024)   * 32 + b];
        i_n += p[(u + 2048)   * 32 + b];
    }
    #pragma unroll
    for (int ks = 8; ks < 16; ks++) {
        const float* p = g_part + (size_t)ks * 3072 * 32;
        h_r += p[(u)          * 32 + b];
        h_z += p[(u + 1024)   * 32 + b];
        h_n += p[(u + 2048)   * 32 + b];
    }

    const float* bih = b_ih_all + layer * 3 * HID;
    const float* bhh = b_hh_all + layer * 3 * HID;
    i_r += bih[u];           h_r += bhh[u];
    i_z += bih[u + HID];     h_z += bhh[u + HID];
    i_n += bih[u + 2 * HID]; h_n += bhh[u + 2 * HID];

    float r = 1.0f / (1.0f + expf(-(i_r + h_r)));
    float z = 1.0f / (1.0f + expf(-(i_z + h_z)));
    float n = tanhf(i_n + r * h_n);

    float h_old = g_h[src][layer][b][u];
    g_h[dst][layer][b][u] = (1.0f - z) * n + z * h_old;
}

// ---------------- FC GEMM (split-K, 3xTF32) ----------------------------------
// grid (20, 16). Partials -> g_part[(ks*32+n)*M_FC_PAD + m] (m contiguous so
// the spectral kernel's reduction is coalesced).
__global__ __launch_bounds__(256) void fc_gemm(
    int src, const float* __restrict__ fc_w)
{
    __shared__ float vhi[BATCH][KSLICE_FC + 4];
    __shared__ float vlo[BATCH][KSLICE_FC + 4];

    const int dst  = src ^ 1;
    const int ks   = blockIdx.y;
    const int warp = threadIdx.x >> 5;
    const int lane = threadIdx.x & 31;
    const int g    = lane >> 2;
    const int t    = lane & 3;
    const int m0   = blockIdx.x * 128 + warp * 16;
    const int koff = ks * KSLICE_FC;

    const float* bsrc = &g_h[dst][LAYERS - 1][0][0];
    for (int i = threadIdx.x; i < BATCH * KSLICE_FC; i += 256) {
        int n = i >> 6;              // KSLICE_FC = 64
        int k = i & (KSLICE_FC - 1);
        float f  = bsrc[n * HID + koff + k];
        uint32_t hu = f2tf(f);
        float hf = __uint_as_float(hu);
        vhi[n][k] = hf;
        vlo[n][k] = __uint_as_float(f2tf(f - hf));
    }
    __syncthreads();

    const int r0 = m0 + g;
    const int r1 = r0 + 8;
    const float* pA0 = fc_w + (size_t)r0 * HID + koff + t;
    const float* pA1 = fc_w + (size_t)r1 * HID + koff + t;
    const bool v0 = (r0 < OUTDIM);
    const bool v1 = (r1 < OUTDIM);

    float c[4][4] = {};

    #pragma unroll 4
    for (int k0 = 0; k0 < KSLICE_FC; k0 += 8) {
        float f0 = v0 ? pA0[k0]     : 0.f;
        float f1 = v1 ? pA1[k0]     : 0.f;
        float f2 = v0 ? pA0[k0 + 4] : 0.f;
        float f3 = v1 ? pA1[k0 + 4] : 0.f;

        uint32_t ah0 = f2tf(f0), ah1 = f2tf(f1), ah2 = f2tf(f2), ah3 = f2tf(f3);
        uint32_t al0 = f2tf(f0 - __uint_as_float(ah0));
        uint32_t al1 = f2tf(f1 - __uint_as_float(ah1));
        uint32_t al2 = f2tf(f2 - __uint_as_float(ah2));
        uint32_t al3 = f2tf(f3 - __uint_as_float(ah3));

        #pragma unroll
        for (int nt = 0; nt < 4; nt++) {
            int n = nt * 8 + g;
            uint32_t bh0 = __float_as_uint(vhi[n][k0 + t]);
            uint32_t bh1 = __float_as_uint(vhi[n][k0 + t + 4]);
            uint32_t bl0 = __float_as_uint(vlo[n][k0 + t]);
            uint32_t bl1 = __float_as_uint(vlo[n][k0 + t + 4]);
            mma1688(c[nt][0], c[nt][1], c[nt][2], c[nt][3], ah0, ah1, ah2, ah3, bh0, bh1);
            mma1688(c[nt][0], c[nt][1], c[nt][2], c[nt][3], ah0, ah1, ah2, ah3, bl0, bl1);
            mma1688(c[nt][0], c[nt][1], c[nt][2], c[nt][3], al0, al1, al2, al3, bh0, bh1);
        }
    }

    // store: layout [ks][n][m], m contiguous
    #pragma unroll
    for (int nt = 0; nt < 4; nt++) {
        #pragma unroll
        for (int j = 0; j < 4; j++) {
            int n = nt * 8 + 2 * t + (j & 1);
            int m = m0 + g + ((j >> 1) * 8);
            if (m < OUTDIM)
                g_part[((size_t)ks * 32 + n) * M_FC_PAD + m] = c[nt][j];
        }
    }
}

// ---------------- spectral crop: FC reduce+bias, DFT, feedback ---------------
__global__ __launch_bounds__(256) void spectral_kernel(
    const float* __restrict__ fc_b, float* __restrict__ outp)
{
    const int b = blockIdx.x;
    __shared__ float a[OUTDIM];
    __shared__ float cre[GRID_N * MODES];
    __shared__ float cim[GRID_N * MODES];

    for (int i = threadIdx.x; i < OUTDIM; i += blockDim.x) {
        float s = fc_b[i];
        #pragma unroll
        for (int ks = 0; ks < KS_FC; ks++)
            s += g_part[((size_t)ks * 32 + b) * M_FC_PAD + i];
        a[i] = s;
        outp[b * OUTDIM + i] = s;
    }
    __syncthreads();

    for (int i = threadIdx.x; i < GRID_N * MODES; i += blockDim.x) {
        int m = i / MODES;
        int q = i % MODES;
        float sre = 0.f, sim = 0.f;
        #pragma unroll 5
        for (int n = 0; n < GRID_N; n++) {
            float v = a[m * GRID_N + n];
            sre += v * g_ct[q][n];
            sim -= v * g_st[q][n];
        }
        cre[m * MODES + q] = sre;
        cim[m * MODES + q] = sim;
    }
    __syncthreads();

    for (int i = threadIdx.x; i < MODES * MODES; i += blockDim.x) {
        int p = i / MODES;
        int q = i % MODES;
        float s = 0.f;
        #pragma unroll 5
        for (int m = 0; m < GRID_N; m++)
            s += g_ct[p][m] * cre[m * MODES + q] + g_st[p][m] * cim[m * MODES + q];
        g_x[b][i] = s;
    }
}

// ---------------- driver -----------------------------------------------------
extern "C" void kernel_launch(void* const* d_in, const int* in_sizes, int n_in,
                              void* d_out, int out_size)
{
    const float* x     = (const float*)d_in[0];
    const float* W_ih  = (const float*)d_in[1];
    const float* W_hh  = (const float*)d_in[2];
    const float* b_ih  = (const float*)d_in[3];
    const float* b_hh  = (const float*)d_in[4];
    const float* fc_w  = (const float*)d_in[5];
    const float* fc_b  = (const float*)d_in[6];
    float*       out   = (float*)d_out;

    init_kernel<<<64, 256>>>(x);

    dim3 ggrid(24, KS);
    dim3 fgrid(20, KS_FC);

    for (int t = 0; t < TIME; t++) {
        int src = t & 1;
        float* outp = out + (size_t)t * BATCH * OUTDIM;

        for (int l = 0; l < LAYERS; l++) {
            gru_gemm<<<ggrid, 256>>>(l, src, W_ih, W_hh);
            gru_cell<<<128, 256>>>(l, src, b_ih, b_hh);
        }
        fc_gemm<<<fgrid, 256>>>(src, fc_w);
        spectral_kernel<<<BATCH, 256>>>(fc_b, outp);
    }
}

// round 3
// speedup vs baseline: 3.9650x; 1.0791x over previous
#include <cuda_runtime.h>
#include <cstdint>

#define HID    1024
#define BATCH  32
#define LAYERS 3
#define OUTDIM 2500
#define GRID_N 50
#define MODES  32
#define TIME   64

#define KS      16          // K-slices for GRU gemm (8 ih + 8 hh)
#define KSLICE  128         // K per slice (GRU)
#define KS_FC   16
#define KSLICE_FC 64
#define M_FC_PAD 2512

// ---------------- persistent device state ------------------------------------
__device__ float g_h[2][LAYERS][BATCH][HID];     // double-buffered hidden state
__device__ float g_x[BATCH][HID];                // spectral feedback input
__device__ float g_ct[MODES][GRID_N];
__device__ float g_st[MODES][GRID_N];
__device__ float g_part[KS * 3072 * 32];         // split-K partials (6.3 MB)

// ---------------- helpers ----------------------------------------------------
__device__ __forceinline__ uint32_t f2tf(float f) {
    uint32_t u;
    asm("cvt.rna.tf32.f32 %0, %1;" : "=r"(u) : "f"(f));
    return u;
}

__device__ __forceinline__ void mma1688(float& c0, float& c1, float& c2, float& c3,
                                        uint32_t a0, uint32_t a1, uint32_t a2, uint32_t a3,
                                        uint32_t b0, uint32_t b1) {
    asm volatile(
        "mma.sync.aligned.m16n8k8.row.col.f32.tf32.tf32.f32 "
        "{%0,%1,%2,%3}, {%4,%5,%6,%7}, {%8,%9}, {%0,%1,%2,%3};"
        : "+f"(c0), "+f"(c1), "+f"(c2), "+f"(c3)
        : "r"(a0), "r"(a1), "r"(a2), "r"(a3), "r"(b0), "r"(b1));
}

// ---------------- init -------------------------------------------------------
__global__ void init_kernel(const float* __restrict__ x)
{
    int tid    = blockIdx.x * blockDim.x + threadIdx.x;
    int stride = gridDim.x * blockDim.x;

    float* hflat = (float*)g_h;
    for (int i = tid; i < 2 * LAYERS * BATCH * HID; i += stride) hflat[i] = 0.0f;

    float* xflat = (float*)g_x;
    for (int i = tid; i < BATCH * HID; i += stride) xflat[i] = x[i];

    for (int i = tid; i < MODES * GRID_N; i += stride) {
        int t = i / GRID_N;
        int n = i % GRID_N;
        float arg = 2.0f * (float)(t - 16) * (float)n / 50.0f;  // units of pi
        g_ct[t][n] = cospif(arg);
        g_st[t][n] = sinpif(arg);
    }
}

// ---------------- GRU gate GEMM (split-K, 3xTF32) ----------------------------
// grid (48, 16): x = m-block (64 rows), y = K-slice. Slices 0-7: W_ih @ x,
// slices 8-15: W_hh @ h. Partials -> g_part[ks][m][n] (n = batch).
__global__ __launch_bounds__(128) void gru_gemm(
    int layer, int src,
    const float* __restrict__ W_ih_all,
    const float* __restrict__ W_hh_all)
{
    __shared__ float vhi[BATCH][KSLICE + 4];
    __shared__ float vlo[BATCH][KSLICE + 4];

    const int dst  = src ^ 1;
    const int ks   = blockIdx.y;
    const int warp = threadIdx.x >> 5;
    const int lane = threadIdx.x & 31;
    const int g    = lane >> 2;      // groupID
    const int t    = lane & 3;       // threadID_in_group
    const int m0   = blockIdx.x * 64 + warp * 16;
    const int koff = (ks & 7) * KSLICE;

    // stage B slice (transposed, hi/lo split)
    const float* bsrc;
    if (ks < 8) {
        bsrc = (layer == 0) ? &g_x[0][0] : &g_h[dst][layer - 1][0][0];
    } else {
        bsrc = &g_h[src][layer][0][0];
    }
    #pragma unroll 4
    for (int i = threadIdx.x; i < BATCH * KSLICE; i += 128) {
        int n = i >> 7;              // KSLICE = 128
        int k = i & (KSLICE - 1);
        float f  = bsrc[n * HID + koff + k];
        uint32_t hu = f2tf(f);
        float hf = __uint_as_float(hu);
        vhi[n][k] = hf;
        vlo[n][k] = __uint_as_float(f2tf(f - hf));
    }
    __syncthreads();

    // A row pointers (weights, fp32 in global)
    const float* A = ((ks < 8) ? W_ih_all : W_hh_all) + (size_t)layer * 3 * HID * HID;
    const float* pA0 = A + (size_t)(m0 + g) * HID + koff + t;
    const float* pA1 = pA0 + (size_t)8 * HID;

    float c[4][4] = {};

    #pragma unroll 8
    for (int k0 = 0; k0 < KSLICE; k0 += 8) {
        float f0 = pA0[k0];
        float f1 = pA1[k0];
        float f2 = pA0[k0 + 4];
        float f3 = pA1[k0 + 4];

        uint32_t ah0 = f2tf(f0), ah1 = f2tf(f1), ah2 = f2tf(f2), ah3 = f2tf(f3);
        uint32_t al0 = f2tf(f0 - __uint_as_float(ah0));
        uint32_t al1 = f2tf(f1 - __uint_as_float(ah1));
        uint32_t al2 = f2tf(f2 - __uint_as_float(ah2));
        uint32_t al3 = f2tf(f3 - __uint_as_float(ah3));

        #pragma unroll
        for (int nt = 0; nt < 4; nt++) {
            int n = nt * 8 + g;
            uint32_t bh0 = __float_as_uint(vhi[n][k0 + t]);
            uint32_t bh1 = __float_as_uint(vhi[n][k0 + t + 4]);
            uint32_t bl0 = __float_as_uint(vlo[n][k0 + t]);
            uint32_t bl1 = __float_as_uint(vlo[n][k0 + t + 4]);
            mma1688(c[nt][0], c[nt][1], c[nt][2], c[nt][3], ah0, ah1, ah2, ah3, bh0, bh1);
            mma1688(c[nt][0], c[nt][1], c[nt][2], c[nt][3], ah0, ah1, ah2, ah3, bl0, bl1);
            mma1688(c[nt][0], c[nt][1], c[nt][2], c[nt][3], al0, al1, al2, al3, bh0, bh1);
        }
    }

    // store partials: g_part[ks][m][n], n contiguous
    #pragma unroll
    for (int nt = 0; nt < 4; nt++) {
        int n = nt * 8 + 2 * t;
        float* base = g_part + ((size_t)ks * 3072 + (m0 + g)) * 32 + n;
        *(float2*)base            = make_float2(c[nt][0], c[nt][1]);
        *(float2*)(base + 8 * 32) = make_float2(c[nt][2], c[nt][3]);
    }
}

// ---------------- GRU cell pointwise: reduce partials + gate math ------------
__global__ __launch_bounds__(256) void gru_cell(
    int layer, int src,
    const float* __restrict__ b_ih_all,
    const float* __restrict__ b_hh_all)
{
    const int dst = src ^ 1;
    const int gid = blockIdx.x * 256 + threadIdx.x;
    const int b   = gid & 31;
    const int u   = gid >> 5;

    float i_r = 0.f, i_z = 0.f, i_n = 0.f, h_r = 0.f, h_z = 0.f, h_n = 0.f;
    #pragma unroll
    for (int ks = 0; ks < 8; ks++) {
        const float* p = g_part + (size_t)ks * 3072 * 32;
        i_r += p[(u)          * 32 + b];
        i_z += p[(u + 1024)   * 32 + b];
        i_n += p[(u + 2048)   * 32 + b];
    }
    #pragma unroll
    for (int ks = 8; ks < 16; ks++) {
        const float* p = g_part + (size_t)ks * 3072 * 32;
        h_r += p[(u)          * 32 + b];
        h_z += p[(u + 1024)   * 32 + b];
        h_n += p[(u + 2048)   * 32 + b];
    }

    const float* bih = b_ih_all + layer * 3 * HID;
    const float* bhh = b_hh_all + layer * 3 * HID;
    i_r += bih[u];           h_r += bhh[u];
    i_z += bih[u + HID];     h_z += bhh[u + HID];
    i_n += bih[u + 2 * HID]; h_n += bhh[u + 2 * HID];

    float r = 1.0f / (1.0f + expf(-(i_r + h_r)));
    float z = 1.0f / (1.0f + expf(-(i_z + h_z)));
    float n = tanhf(i_n + r * h_n);

    float h_old = g_h[src][layer][b][u];
    g_h[dst][layer][b][u] = (1.0f - z) * n + z * h_old;
}

// ---------------- FC GEMM (split-K, 3xTF32) ----------------------------------
// grid (40, 16). Partials -> g_part[(ks*32+n)*M_FC_PAD + m] (m contiguous so
// the spectral kernel's reduction is coalesced).
__global__ __launch_bounds__(128) void fc_gemm(
    int src, const float* __restrict__ fc_w)
{
    __shared__ float vhi[BATCH][KSLICE_FC + 4];
    __shared__ float vlo[BATCH][KSLICE_FC + 4];

    const int dst  = src ^ 1;
    const int ks   = blockIdx.y;
    const int warp = threadIdx.x >> 5;
    const int lane = threadIdx.x & 31;
    const int g    = lane >> 2;
    const int t    = lane & 3;
    const int m0   = blockIdx.x * 64 + warp * 16;
    const int koff = ks * KSLICE_FC;

    const float* bsrc = &g_h[dst][LAYERS - 1][0][0];
    #pragma unroll 4
    for (int i = threadIdx.x; i < BATCH * KSLICE_FC; i += 128) {
        int n = i >> 6;              // KSLICE_FC = 64
        int k = i & (KSLICE_FC - 1);
        float f  = bsrc[n * HID + koff + k];
        uint32_t hu = f2tf(f);
        float hf = __uint_as_float(hu);
        vhi[n][k] = hf;
        vlo[n][k] = __uint_as_float(f2tf(f - hf));
    }
    __syncthreads();

    const int r0 = m0 + g;
    const int r1 = r0 + 8;
    const float* pA0 = fc_w + (size_t)r0 * HID + koff + t;
    const float* pA1 = fc_w + (size_t)r1 * HID + koff + t;
    const bool v0 = (r0 < OUTDIM);
    const bool v1 = (r1 < OUTDIM);

    float c[4][4] = {};

    #pragma unroll 8
    for (int k0 = 0; k0 < KSLICE_FC; k0 += 8) {
        float f0 = v0 ? pA0[k0]     : 0.f;
        float f1 = v1 ? pA1[k0]     : 0.f;
        float f2 = v0 ? pA0[k0 + 4] : 0.f;
        float f3 = v1 ? pA1[k0 + 4] : 0.f;

        uint32_t ah0 = f2tf(f0), ah1 = f2tf(f1), ah2 = f2tf(f2), ah3 = f2tf(f3);
        uint32_t al0 = f2tf(f0 - __uint_as_float(ah0));
        uint32_t al1 = f2tf(f1 - __uint_as_float(ah1));
        uint32_t al2 = f2tf(f2 - __uint_as_float(ah2));
        uint32_t al3 = f2tf(f3 - __uint_as_float(ah3));

        #pragma unroll
        for (int nt = 0; nt < 4; nt++) {
            int n = nt * 8 + g;
            uint32_t bh0 = __float_as_uint(vhi[n][k0 + t]);
            uint32_t bh1 = __float_as_uint(vhi[n][k0 + t + 4]);
            uint32_t bl0 = __float_as_uint(vlo[n][k0 + t]);
            uint32_t bl1 = __float_as_uint(vlo[n][k0 + t + 4]);
            mma1688(c[nt][0], c[nt][1], c[nt][2], c[nt][3], ah0, ah1, ah2, ah3, bh0, bh1);
            mma1688(c[nt][0], c[nt][1], c[nt][2], c[nt][3], ah0, ah1, ah2, ah3, bl0, bl1);
            mma1688(c[nt][0], c[nt][1], c[nt][2], c[nt][3], al0, al1, al2, al3, bh0, bh1);
        }
    }

    // store: layout [ks][n][m], m contiguous
    #pragma unroll
    for (int nt = 0; nt < 4; nt++) {
        #pragma unroll
        for (int j = 0; j < 4; j++) {
            int n = nt * 8 + 2 * t + (j & 1);
            int m = m0 + g + ((j >> 1) * 8);
            if (m < OUTDIM)
                g_part[((size_t)ks * 32 + n) * M_FC_PAD + m] = c[nt][j];
        }
    }
}

// ---------------- spectral crop: FC reduce+bias, DFT, feedback ---------------
__global__ __launch_bounds__(256) void spectral_kernel(
    const float* __restrict__ fc_b, float* __restrict__ outp)
{
    const int b = blockIdx.x;
    __shared__ float a[OUTDIM];
    __shared__ float cre[GRID_N * MODES];
    __shared__ float cim[GRID_N * MODES];

    for (int i = threadIdx.x; i < OUTDIM; i += blockDim.x) {
        float s = fc_b[i];
        #pragma unroll
        for (int ks = 0; ks < KS_FC; ks++)
            s += g_part[((size_t)ks * 32 + b) * M_FC_PAD + i];
        a[i] = s;
        outp[b * OUTDIM + i] = s;
    }
    __syncthreads();

    for (int i = threadIdx.x; i < GRID_N * MODES; i += blockDim.x) {
        int m = i / MODES;
        int q = i % MODES;
        float sre = 0.f, sim = 0.f;
        #pragma unroll 5
        for (int n = 0; n < GRID_N; n++) {
            float v = a[m * GRID_N + n];
            sre += v * g_ct[q][n];
            sim -= v * g_st[q][n];
        }
        cre[m * MODES + q] = sre;
        cim[m * MODES + q] = sim;
    }
    __syncthreads();

    for (int i = threadIdx.x; i < MODES * MODES; i += blockDim.x) {
        int p = i / MODES;
        int q = i % MODES;
        float s = 0.f;
        #pragma unroll 5
        for (int m = 0; m < GRID_N; m++)
            s += g_ct[p][m] * cre[m * MODES + q] + g_st[p][m] * cim[m * MODES + q];
        g_x[b][i] = s;
    }
}

// ---------------- driver -----------------------------------------------------
extern "C" void kernel_launch(void* const* d_in, const int* in_sizes, int n_in,
                              void* d_out, int out_size)
{
    const float* x     = (const float*)d_in[0];
    const float* W_ih  = (const float*)d_in[1];
    const float* W_hh  = (const float*)d_in[2];
    const float* b_ih  = (const float*)d_in[3];
    const float* b_hh  = (const float*)d_in[4];
    const float* fc_w  = (const float*)d_in[5];
    const float* fc_b  = (const float*)d_in[6];
    float*       out   = (float*)d_out;

    init_kernel<<<64, 256>>>(x);

    dim3 ggrid(48, KS);
    dim3 fgrid(40, KS_FC);

    for (int t = 0; t < TIME; t++) {
        int src = t & 1;
        float* outp = out + (size_t)t * BATCH * OUTDIM;

        for (int l = 0; l < LAYERS; l++) {
            gru_gemm<<<ggrid, 128>>>(l, src, W_ih, W_hh);
            gru_cell<<<128, 256>>>(l, src, b_ih, b_hh);
        }
        fc_gemm<<<fgrid, 128>>>(src, fc_w);
        spectral_kernel<<<BATCH, 256>>>(fc_b, outp);
    }
}

// round 5
// speedup vs baseline: 4.3345x; 1.0932x over previous
#include <cuda_runtime.h>
#include <cstdint>

#define HID    1024
#define BATCH  32
#define LAYERS 3
#define OUTDIM 2500
#define GRID_N 50
#define MODES  32
#define TIME   64

#define KS      16          // K-slices for GRU gemm (8 ih + 8 hh)
#define KSLICE  128         // K per slice (GRU)
#define KS_FC   16
#define KSLICE_FC 64
#define M_FC_PAD 2512

#define GRU_MT  192         // 3072/16 m-tiles per GRU matrix
#define GRU_KT  128         // 1024/8  k-tiles
#define FC_MT   160         // padded 2560/16
#define FC_KT   128

// ---------------- persistent device state ------------------------------------
__device__ float g_h[2][LAYERS][BATCH][HID];     // double-buffered hidden state
__device__ float g_x[BATCH][HID];                // spectral feedback input
__device__ float g_ct[MODES][GRID_N];
__device__ float g_st[MODES][GRID_N];
__device__ float g_part[KS * 3072 * 32];         // split-K partials (6.3 MB)

// fragment-swizzled weights: [mat][mt][kt][lane*4+e], mat = layer*2 + (0=ih,1=hh)
__device__ float g_Wsw[6 * GRU_MT * GRU_KT * 128];   // 75.5 MB
__device__ float g_Fsw[FC_MT * FC_KT * 128];         // 10.5 MB (zero padded)

// ---------------- helpers ----------------------------------------------------
__device__ __forceinline__ uint32_t f2tf(float f) {
    uint32_t u;
    asm("cvt.rna.tf32.f32 %0, %1;" : "=r"(u) : "f"(f));
    return u;
}

__device__ __forceinline__ void mma1688(float& c0, float& c1, float& c2, float& c3,
                                        uint32_t a0, uint32_t a1, uint32_t a2, uint32_t a3,
                                        uint32_t b0, uint32_t b1) {
    asm volatile(
        "mma.sync.aligned.m16n8k8.row.col.f32.tf32.tf32.f32 "
        "{%0,%1,%2,%3}, {%4,%5,%6,%7}, {%8,%9}, {%0,%1,%2,%3};"
        : "+f"(c0), "+f"(c1), "+f"(c2), "+f"(c3)
        : "r"(a0), "r"(a1), "r"(a2), "r"(a3), "r"(b0), "r"(b1));
}

// ---------------- init -------------------------------------------------------
__global__ void init_kernel(const float* __restrict__ x)
{
    int tid    = blockIdx.x * blockDim.x + threadIdx.x;
    int stride = gridDim.x * blockDim.x;

    float* hflat = (float*)g_h;
    for (int i = tid; i < 2 * LAYERS * BATCH * HID; i += stride) hflat[i] = 0.0f;

    float* xflat = (float*)g_x;
    for (int i = tid; i < BATCH * HID; i += stride) xflat[i] = x[i];

    for (int i = tid; i < MODES * GRID_N; i += stride) {
        int t = i / GRID_N;
        int n = i % GRID_N;
        float arg = 2.0f * (float)(t - 16) * (float)n / 50.0f;  // units of pi
        g_ct[t][n] = cospif(arg);
        g_st[t][n] = sinpif(arg);
    }
}

// ---------------- weight repack into fragment order --------------------------
// layout: [mat][mt][kt][lane*4+e]; per-tile = 128 floats = 7 bits.
// frag element e of lane (g,t) in tile (mt,kt):
//   e0=(g,t) e1=(g+8,t) e2=(g,t+4) e3=(g+8,t+4)
__global__ void repack_gru(const float* __restrict__ W_ih,
                           const float* __restrict__ W_hh)
{
    int64_t total = (int64_t)6 * GRU_MT * GRU_KT * 128;
    for (int64_t idx = (int64_t)blockIdx.x * blockDim.x + threadIdx.x;
         idx < total; idx += (int64_t)gridDim.x * blockDim.x) {
        int within = (int)(idx & 127);         // lane*4 + e
        int e    = within & 3;
        int lane = within >> 2;
        int kt   = (int)((idx >> 7) & (GRU_KT - 1));
        int tmp  = (int)(idx >> 14);           // mat*GRU_MT + mt
        int mt   = tmp % GRU_MT;
        int mat  = tmp / GRU_MT;
        int layer = mat >> 1;
        const float* src = ((mat & 1) ? W_hh : W_ih) + (size_t)layer * 3 * HID * HID;
        int g = lane >> 2, t = lane & 3;
        int r = mt * 16 + g + (e & 1) * 8;
        int c = kt * 8 + t + (e >> 1) * 4;
        g_Wsw[idx] = src[(size_t)r * HID + c];
    }
}

__global__ void repack_fc(const float* __restrict__ fc_w)
{
    int64_t total = (int64_t)FC_MT * FC_KT * 128;
    for (int64_t idx = (int64_t)blockIdx.x * blockDim.x + threadIdx.x;
         idx < total; idx += (int64_t)gridDim.x * blockDim.x) {
        int within = (int)(idx & 127);
        int e    = within & 3;
        int lane = within >> 2;
        int kt   = (int)((idx >> 7) & (FC_KT - 1));
        int mt   = (int)(idx >> 14);
        int g = lane >> 2, t = lane & 3;
        int r = mt * 16 + g + (e & 1) * 8;
        int c = kt * 8 + t + (e >> 1) * 4;
        g_Fsw[idx] = (r < OUTDIM) ? fc_w[(size_t)r * HID + c] : 0.0f;
    }
}

// ---------------- GRU gate GEMM (split-K, 3xTF32, swizzled A) ----------------
// grid (48, 16): x = m-block (64 rows), y = K-slice. Slices 0-7: W_ih @ x,
// slices 8-15: W_hh @ h. Partials -> g_part[ks][m][n].
__global__ __launch_bounds__(128) void gru_gemm(int layer, int src)
{
    __shared__ float vhi[BATCH][KSLICE + 4];
    __shared__ float vlo[BATCH][KSLICE + 4];

    const int dst  = src ^ 1;
    const int ks   = blockIdx.y;
    const int warp = threadIdx.x >> 5;
    const int lane = threadIdx.x & 31;
    const int g    = lane >> 2;
    const int t    = lane & 3;
    const int m0   = blockIdx.x * 64 + warp * 16;
    const int koff = (ks & 7) * KSLICE;

    // stage B slice (transposed, hi/lo split)
    const float* bsrc;
    if (ks < 8) {
        bsrc = (layer == 0) ? &g_x[0][0] : &g_h[dst][layer - 1][0][0];
    } else {
        bsrc = &g_h[src][layer][0][0];
    }
    #pragma unroll 4
    for (int i = threadIdx.x; i < BATCH * KSLICE; i += 128) {
        int n = i >> 7;              // KSLICE = 128
        int k = i & (KSLICE - 1);
        float f  = bsrc[n * HID + koff + k];
        uint32_t hu = f2tf(f);
        float hf = __uint_as_float(hu);
        vhi[n][k] = hf;
        vlo[n][k] = __uint_as_float(f2tf(f - hf));
    }
    __syncthreads();

    // swizzled A fragments: one LDG.128 per lane per 16x8 tile
    const int mat = layer * 2 + (ks >> 3);
    const int mt  = blockIdx.x * 4 + warp;
    const int kt0 = (ks & 7) * 16;
    const float4* pA = (const float4*)(g_Wsw
                     + (((size_t)mat * GRU_MT + mt) * GRU_KT + kt0) * 128) + lane;

    float c[4][4] = {};

    #pragma unroll
    for (int kt = 0; kt < 16; kt++) {
        float4 fr = pA[kt * 32];
        int k0 = kt * 8;

        uint32_t ah0 = f2tf(fr.x), ah1 = f2tf(fr.y), ah2 = f2tf(fr.z), ah3 = f2tf(fr.w);
        uint32_t al0 = f2tf(fr.x - __uint_as_float(ah0));
        uint32_t al1 = f2tf(fr.y - __uint_as_float(ah1));
        uint32_t al2 = f2tf(fr.z - __uint_as_float(ah2));
        uint32_t al3 = f2tf(fr.w - __uint_as_float(ah3));

        #pragma unroll
        for (int nt = 0; nt < 4; nt++) {
            int n = nt * 8 + g;
            uint32_t bh0 = __float_as_uint(vhi[n][k0 + t]);
            uint32_t bh1 = __float_as_uint(vhi[n][k0 + t + 4]);
            uint32_t bl0 = __float_as_uint(vlo[n][k0 + t]);
            uint32_t bl1 = __float_as_uint(vlo[n][k0 + t + 4]);
            mma1688(c[nt][0], c[nt][1], c[nt][2], c[nt][3], ah0, ah1, ah2, ah3, bh0, bh1);
            mma1688(c[nt][0], c[nt][1], c[nt][2], c[nt][3], ah0, ah1, ah2, ah3, bl0, bl1);
            mma1688(c[nt][0], c[nt][1], c[nt][2], c[nt][3], al0, al1, al2, al3, bh0, bh1);
        }
    }

    // store partials: g_part[ks][m][n], n contiguous
    #pragma unroll
    for (int nt = 0; nt < 4; nt++) {
        int n = nt * 8 + 2 * t;
        float* base = g_part + ((size_t)ks * 3072 + (m0 + g)) * 32 + n;
        *(float2*)base            = make_float2(c[nt][0], c[nt][1]);
        *(float2*)(base + 8 * 32) = make_float2(c[nt][2], c[nt][3]);
    }
}

// ---------------- GRU cell pointwise: reduce partials + gate math ------------
__global__ __launch_bounds__(256) void gru_cell(
    int layer, int src,
    const float* __restrict__ b_ih_all,
    const float* __restrict__ b_hh_all)
{
    const int dst = src ^ 1;
    const int gid = blockIdx.x * 256 + threadIdx.x;
    const int b   = gid & 31;
    const int u   = gid >> 5;

    float i_r = 0.f, i_z = 0.f, i_n = 0.f, h_r = 0.f, h_z = 0.f, h_n = 0.f;
    #pragma unroll
    for (int ks = 0; ks < 8; ks++) {
        const float* p = g_part + (size_t)ks * 3072 * 32;
        i_r += p[(u)          * 32 + b];
        i_z += p[(u + 1024)   * 32 + b];
        i_n += p[(u + 2048)   * 32 + b];
    }
    #pragma unroll
    for (int ks = 8; ks < 16; ks++) {
        const float* p = g_part + (size_t)ks * 3072 * 32;
        h_r += p[(u)          * 32 + b];
        h_z += p[(u + 1024)   * 32 + b];
        h_n += p[(u + 2048)   * 32 + b];
    }

    const float* bih = b_ih_all + layer * 3 * HID;
    const float* bhh = b_hh_all + layer * 3 * HID;
    i_r += bih[u];           h_r += bhh[u];
    i_z += bih[u + HID];     h_z += bhh[u + HID];
    i_n += bih[u + 2 * HID]; h_n += bhh[u + 2 * HID];

    float r = 1.0f / (1.0f + expf(-(i_r + h_r)));
    float z = 1.0f / (1.0f + expf(-(i_z + h_z)));
    float n = tanhf(i_n + r * h_n);

    float h_old = g_h[src][layer][b][u];
    g_h[dst][layer][b][u] = (1.0f - z) * n + z * h_old;
}

// ---------------- FC GEMM (split-K, 3xTF32, swizzled A) ----------------------
// grid (40, 16). Partials -> g_part[(ks*32+n)*M_FC_PAD + m].
__global__ __launch_bounds__(128) void fc_gemm(int src)
{
    __shared__ float vhi[BATCH][KSLICE_FC + 4];
    __shared__ float vlo[BATCH][KSLICE_FC + 4];

    const int dst  = src ^ 1;
    const int ks   = blockIdx.y;
    const int warp = threadIdx.x >> 5;
    const int lane = threadIdx.x & 31;
    const int g    = lane >> 2;
    const int t    = lane & 3;
    const int m0   = blockIdx.x * 64 + warp * 16;
    const int koff = ks * KSLICE_FC;

    const float* bsrc = &g_h[dst][LAYERS - 1][0][0];
    #pragma unroll 4
    for (int i = threadIdx.x; i < BATCH * KSLICE_FC; i += 128) {
        int n = i >> 6;              // KSLICE_FC = 64
        int k = i & (KSLICE_FC - 1);
        float f  = bsrc[n * HID + koff + k];
        uint32_t hu = f2tf(f);
        float hf = __uint_as_float(hu);
        vhi[n][k] = hf;
        vlo[n][k] = __uint_as_float(f2tf(f - hf));
    }
    __syncthreads();

    const int mt  = blockIdx.x * 4 + warp;
    const int kt0 = ks * 8;                  // KSLICE_FC/8 = 8 tiles
    const float4* pA = (const float4*)(g_Fsw
                     + ((size_t)mt * FC_KT + kt0) * 128) + lane;

    float c[4][4] = {};

    #pragma unroll
    for (int kt = 0; kt < 8; kt++) {
        float4 fr = pA[kt * 32];
        int k0 = kt * 8;

        uint32_t ah0 = f2tf(fr.x), ah1 = f2tf(fr.y), ah2 = f2tf(fr.z), ah3 = f2tf(fr.w);
        uint32_t al0 = f2tf(fr.x - __uint_as_float(ah0));
        uint32_t al1 = f2tf(fr.y - __uint_as_float(ah1));
        uint32_t al2 = f2tf(fr.z - __uint_as_float(ah2));
        uint32_t al3 = f2tf(fr.w - __uint_as_float(ah3));

        #pragma unroll
        for (int nt = 0; nt < 4; nt++) {
            int n = nt * 8 + g;
            uint32_t bh0 = __float_as_uint(vhi[n][k0 + t]);
            uint32_t bh1 = __float_as_uint(vhi[n][k0 + t + 4]);
            uint32_t bl0 = __float_as_uint(vlo[n][k0 + t]);
            uint32_t bl1 = __float_as_uint(vlo[n][k0 + t + 4]);
            mma1688(c[nt][0], c[nt][1], c[nt][2], c[nt][3], ah0, ah1, ah2, ah3, bh0, bh1);
            mma1688(c[nt][0], c[nt][1], c[nt][2], c[nt][3], ah0, ah1, ah2, ah3, bl0, bl1);
            mma1688(c[nt][0], c[nt][1], c[nt][2], c[nt][3], al0, al1, al2, al3, bh0, bh1);
        }
    }

    // store: layout [ks][n][m], m contiguous
    #pragma unroll
    for (int nt = 0; nt < 4; nt++) {
        #pragma unroll
        for (int j = 0; j < 4; j++) {
            int n = nt * 8 + 2 * t + (j & 1);
            int m = m0 + g + ((j >> 1) * 8);
            if (m < OUTDIM)
                g_part[((size_t)ks * 32 + n) * M_FC_PAD + m] = c[nt][j];
        }
    }
}

// ---------------- spectral crop: FC reduce+bias, DFT, feedback ---------------
__global__ __launch_bounds__(256) void spectral_kernel(
    const float* __restrict__ fc_b, float* __restrict__ outp)
{
    const int b = blockIdx.x;
    __shared__ float a[OUTDIM];
    __shared__ float cre[GRID_N * MODES];
    __shared__ float cim[GRID_N * MODES];

    for (int i = threadIdx.x; i < OUTDIM; i += blockDim.x) {
        float s = fc_b[i];
        #pragma unroll
        for (int ks = 0; ks < KS_FC; ks++)
            s += g_part[((size_t)ks * 32 + b) * M_FC_PAD + i];
        a[i] = s;
        outp[b * OUTDIM + i] = s;
    }
    __syncthreads();

    for (int i = threadIdx.x; i < GRID_N * MODES; i += blockDim.x) {
        int m = i / MODES;
        int q = i % MODES;
        float sre = 0.f, sim = 0.f;
        #pragma unroll 5
        for (int n = 0; n < GRID_N; n++) {
            float v = a[m * GRID_N + n];
            sre += v * g_ct[q][n];
            sim -= v * g_st[q][n];
        }
        cre[m * MODES + q] = sre;
        cim[m * MODES + q] = sim;
    }
    __syncthreads();

    for (int i = threadIdx.x; i < MODES * MODES; i += blockDim.x) {
        int p = i / MODES;
        int q = i % MODES;
        float s = 0.f;
        #pragma unroll 5
        for (int m = 0; m < GRID_N; m++)
            s += g_ct[p][m] * cre[m * MODES + q] + g_st[p][m] * cim[m * MODES + q];
        g_x[b][i] = s;
    }
}

// ---------------- driver -----------------------------------------------------
extern "C" void kernel_launch(void* const* d_in, const int* in_sizes, int n_in,
                              void* d_out, int out_size)
{
    const float* x     = (const float*)d_in[0];
    const float* W_ih  = (const float*)d_in[1];
    const float* W_hh  = (const float*)d_in[2];
    const float* b_ih  = (const float*)d_in[3];
    const float* b_hh  = (const float*)d_in[4];
    const float* fc_w  = (const float*)d_in[5];
    const float* fc_b  = (const float*)d_in[6];
    float*       out   = (float*)d_out;

    init_kernel<<<64, 256>>>(x);
    repack_gru<<<592, 256>>>(W_ih, W_hh);
    repack_fc<<<128, 256>>>(fc_w);

    dim3 ggrid(48, KS);
    dim3 fgrid(40, KS_FC);

    for (int t = 0; t < TIME; t++) {
        int src = t & 1;
        float* outp = out + (size_t)t * BATCH * OUTDIM;

        for (int l = 0; l < LAYERS; l++) {
            gru_gemm<<<ggrid, 128>>>(l, src);
            gru_cell<<<128, 256>>>(l, src, b_ih, b_hh);
        }
        fc_gemm<<<fgrid, 128>>>(src);
        spectral_kernel<<<BATCH, 256>>>(fc_b, outp);
    }
}